// round 3
// baseline (speedup 1.0000x reference)
#include <cuda_runtime.h>

#define D_ 160
#define H_ 192
#define W_ 160
#define HW_ (H_ * W_)
#define N_ (D_ * H_ * W_)          // 4,915,200
#define R_ 4
#define WSZ 729.0f

#define DCH 80                      // d-chunk in pass A (2 chunks)
#define NBLK_WD (H_ * 2)            // 384 boxWD blocks
#define GBLK 512                    // grad blocks appended to pass A
#define HCH 96                      // h-chunk in pass B (2 chunks)
#define NBLK_B (D_ * 2)             // 320 pass-B blocks
#define TPB 160

// Scratch (static device globals)
__device__ float g_B[5u * N_];      // W+D box-summed channels
__device__ float g_ccpart[NBLK_B];
__device__ float g_gpart[GBLK * 3];
__device__ unsigned int g_cnt;

// ---------------------------------------------------------------------------
// Pass A: blocks [0, 2H) do W-boxsum + D-boxsum (ring over d) for one h row.
//         blocks [2H, 2H+GBLK) do the gradient-loss partials.
// ---------------------------------------------------------------------------
__global__ void __launch_bounds__(TPB) k_passA(const float* __restrict__ I,
                                               const float* __restrict__ J,
                                               const float* __restrict__ dsp)
{
    const int bid = blockIdx.x;
    const int w = threadIdx.x;

    if (bid == 0 && w == 0) g_cnt = 0u;   // reset for graph replay

    if (bid < NBLK_WD) {
        // ----- W+D box sum for row h, d-chunk half -----
        __shared__ float ring[9][5][W_];
        __shared__ float sI[W_ + 2 * R_];
        __shared__ float sJ[W_ + 2 * R_];

        const int h  = bid >> 1;
        const int d0 = (bid & 1) * DCH;

        if (w < R_) {
            sI[w] = 0.f; sJ[w] = 0.f;
            sI[W_ + R_ + w] = 0.f; sJ[W_ + R_ + w] = 0.f;
        }

        const float* __restrict__ Ib = I + (size_t)h * W_;
        const float* __restrict__ Jb = J + (size_t)h * W_;

        float S0 = 0.f, S1 = 0.f, S2 = 0.f, S3 = 0.f, S4 = 0.f;

        for (int d = d0 - R_; d < d0 + DCH + R_; d++) {
            __syncthreads();
            const bool valid = (d >= 0) & (d < D_);
            if (valid) {
                sI[w + R_] = Ib[(size_t)d * HW_ + w];
                sJ[w + R_] = Jb[(size_t)d * HW_ + w];
            }
            __syncthreads();

            float ws0 = 0.f, ws1 = 0.f, ws2 = 0.f, ws3 = 0.f, ws4 = 0.f;
            if (valid) {
#pragma unroll
                for (int k = 0; k < 2 * R_ + 1; k++) {
                    float a = sI[w + k];
                    float b = sJ[w + k];
                    ws0 += a; ws1 += b;
                    ws2 += a * a; ws3 += b * b; ws4 += a * b;
                }
            }
            const int slot = (d + 18) % 9;
            ring[slot][0][w] = ws0; S0 += ws0;
            ring[slot][1][w] = ws1; S1 += ws1;
            ring[slot][2][w] = ws2; S2 += ws2;
            ring[slot][3][w] = ws3; S3 += ws3;
            ring[slot][4][w] = ws4; S4 += ws4;

            const int od = d - R_;
            if (od >= d0 && od < d0 + DCH) {
                const size_t o = (size_t)od * HW_ + (size_t)h * W_ + w;
                g_B[0u * N_ + o] = S0;
                g_B[1u * N_ + o] = S1;
                g_B[2u * N_ + o] = S2;
                g_B[3u * N_ + o] = S3;
                g_B[4u * N_ + o] = S4;
            }
            const int dl = d - 2 * R_;
            if (dl >= d0 - R_) {
                const int ls = (dl + 18) % 9;
                S0 -= ring[ls][0][w];
                S1 -= ring[ls][1][w];
                S2 -= ring[ls][2][w];
                S3 -= ring[ls][3][w];
                S4 -= ring[ls][4][w];
            }
        }
    } else {
        // ----- gradient-loss partials (float4 vectorized) -----
        const int gid = bid - NBLK_WD;
        const int W4 = W_ / 4;
        const int NV = N_ / 4;
        const int total = 3 * NV;
        const float4* __restrict__ p4 = (const float4*)dsp;
        const float*  __restrict__ pf = dsp;

        float aH = 0.f, aD = 0.f, aW = 0.f;
        for (int i = gid * TPB + w; i < total; i += GBLK * TPB) {
            const int r  = i % NV;
            const int wv = r % W4;
            const int h  = (r / W4) % H_;
            const int d  = r / (W4 * H_);

            const float4 v = p4[i];
            float t;
            t = v.y - v.x; aW += t * t;
            t = v.z - v.y; aW += t * t;
            t = v.w - v.z; aW += t * t;
            if (wv < W4 - 1) { t = pf[i * 4 + 4] - v.w; aW += t * t; }
            if (h < H_ - 1) {
                const float4 u = p4[i + W4];
                t = u.x - v.x; aH += t * t;
                t = u.y - v.y; aH += t * t;
                t = u.z - v.z; aH += t * t;
                t = u.w - v.w; aH += t * t;
            }
            if (d < D_ - 1) {
                const float4 u = p4[i + HW_ / 4];
                t = u.x - v.x; aD += t * t;
                t = u.y - v.y; aD += t * t;
                t = u.z - v.z; aD += t * t;
                t = u.w - v.w; aD += t * t;
            }
        }

        __shared__ float sh[3][TPB];
        sh[0][w] = aH; sh[1][w] = aD; sh[2][w] = aW;
        __syncthreads();
        if (w < 80) { sh[0][w] += sh[0][w+80]; sh[1][w] += sh[1][w+80]; sh[2][w] += sh[2][w+80]; }
        __syncthreads();
        if (w < 40) { sh[0][w] += sh[0][w+40]; sh[1][w] += sh[1][w+40]; sh[2][w] += sh[2][w+40]; }
        __syncthreads();
        if (w < 20) { sh[0][w] += sh[0][w+20]; sh[1][w] += sh[1][w+20]; sh[2][w] += sh[2][w+20]; }
        __syncthreads();
        if (w < 10) { sh[0][w] += sh[0][w+10]; sh[1][w] += sh[1][w+10]; sh[2][w] += sh[2][w+10]; }
        __syncthreads();
        if (w < 5)  { sh[0][w] += sh[0][w+5];  sh[1][w] += sh[1][w+5];  sh[2][w] += sh[2][w+5];  }
        __syncthreads();
        if (w == 0) {
            g_gpart[gid * 3 + 0] = sh[0][0] + sh[0][1] + sh[0][2] + sh[0][3] + sh[0][4];
            g_gpart[gid * 3 + 1] = sh[1][0] + sh[1][1] + sh[1][2] + sh[1][3] + sh[1][4];
            g_gpart[gid * 3 + 2] = sh[2][0] + sh[2][1] + sh[2][2] + sh[2][3] + sh[2][4];
        }
    }
}

// ---------------------------------------------------------------------------
// Pass B: H running-window box sum fused with cc formula + reduction.
// grid = (D*2), block = 160. Last finishing block combines everything.
// ---------------------------------------------------------------------------
__global__ void __launch_bounds__(TPB) k_passB(float* __restrict__ out)
{
    const int bid = blockIdx.x;
    const int d  = bid >> 1;
    const int h0 = (bid & 1) * HCH;
    const int w  = threadIdx.x;

    const float* __restrict__ B0 = g_B + 0u * N_ + (size_t)d * HW_ + w;
    const float* __restrict__ B1 = g_B + 1u * N_ + (size_t)d * HW_ + w;
    const float* __restrict__ B2 = g_B + 2u * N_ + (size_t)d * HW_ + w;
    const float* __restrict__ B3 = g_B + 3u * N_ + (size_t)d * HW_ + w;
    const float* __restrict__ B4 = g_B + 4u * N_ + (size_t)d * HW_ + w;

    float S0 = 0.f, S1 = 0.f, S2 = 0.f, S3 = 0.f, S4 = 0.f;
    float acc = 0.f;

    for (int h = h0 - R_; h < h0 + HCH + R_; h++) {
        if (h >= 0 && h < H_) {
            const int o = h * W_;
            S0 += B0[o]; S1 += B1[o]; S2 += B2[o]; S3 += B3[o]; S4 += B4[o];
        }
        const int ho = h - R_;
        if (ho >= h0) {
            const float uI = S0 * (1.0f / WSZ);
            const float uJ = S1 * (1.0f / WSZ);
            const float cross = S4 - uJ * S0 - uI * S1 + uI * uJ * WSZ;
            const float Iv = S2 - 2.0f * uI * S0 + uI * uI * WSZ;
            const float Jv = S3 - 2.0f * uJ * S1 + uJ * uJ * WSZ;
            acc += cross * cross / (Iv * Jv + 1e-5f);
        }
        const int hl = h - 2 * R_;
        if (hl >= h0 - R_ && hl >= 0) {        // L1-hit re-read
            const int o = hl * W_;
            S0 -= B0[o]; S1 -= B1[o]; S2 -= B2[o]; S3 -= B3[o]; S4 -= B4[o];
        }
    }

    __shared__ float sh[TPB];
    sh[w] = acc;
    __syncthreads();
    if (w < 80) sh[w] += sh[w + 80]; __syncthreads();
    if (w < 40) sh[w] += sh[w + 40]; __syncthreads();
    if (w < 20) sh[w] += sh[w + 20]; __syncthreads();
    if (w < 10) sh[w] += sh[w + 10]; __syncthreads();
    if (w < 5)  sh[w] += sh[w + 5];  __syncthreads();
    if (w == 0) g_ccpart[bid] = sh[0] + sh[1] + sh[2] + sh[3] + sh[4];

    // ----- last-block final combine -----
    __shared__ bool is_last;
    if (w == 0) {
        __threadfence();
        is_last = (atomicAdd(&g_cnt, 1u) == NBLK_B - 1);
    }
    __syncthreads();
    if (!is_last) return;

    float cc = 0.f;
    for (int i = w; i < NBLK_B; i += TPB) cc += g_ccpart[i];

    const float invNH = 1.0f / (3.0f * D_ * (H_ - 1) * W_);
    const float invND = 1.0f / (3.0f * (D_ - 1) * H_ * W_);
    const float invNW = 1.0f / (3.0f * D_ * H_ * (W_ - 1));

    float g = 0.f;
    for (int i = w; i < GBLK; i += TPB) {
        g += g_gpart[i * 3 + 0] * invNH
           + g_gpart[i * 3 + 1] * invND
           + g_gpart[i * 3 + 2] * invNW;
    }

    __shared__ float shc[TPB];
    __shared__ float shg2[TPB];
    shc[w] = cc; shg2[w] = g;
    __syncthreads();
    if (w < 80) { shc[w] += shc[w+80]; shg2[w] += shg2[w+80]; } __syncthreads();
    if (w < 40) { shc[w] += shc[w+40]; shg2[w] += shg2[w+40]; } __syncthreads();
    if (w < 20) { shc[w] += shc[w+20]; shg2[w] += shg2[w+20]; } __syncthreads();
    if (w < 10) { shc[w] += shc[w+10]; shg2[w] += shg2[w+10]; } __syncthreads();
    if (w < 5)  { shc[w] += shc[w+5];  shg2[w] += shg2[w+5];  } __syncthreads();
    if (w == 0) {
        const float ccsum = shc[0] + shc[1] + shc[2] + shc[3] + shc[4];
        const float gsum  = shg2[0] + shg2[1] + shg2[2] + shg2[3] + shg2[4];
        out[0] = (1.0f - ccsum / (float)N_) + 0.01f * (gsum / 3.0f);
    }
}

extern "C" void kernel_launch(void* const* d_in, const int* in_sizes, int n_in,
                              void* d_out, int out_size)
{
    const float* I   = (const float*)d_in[0];
    const float* J   = (const float*)d_in[1];
    const float* dsp = (const float*)d_in[2];
    float* out = (float*)d_out;

    k_passA<<<NBLK_WD + GBLK, TPB>>>(I, J, dsp);
    k_passB<<<NBLK_B, TPB>>>(out);
}

// round 4
// speedup vs baseline: 1.6299x; 1.6299x over previous
#include <cuda_runtime.h>

#define D_ 160
#define H_ 192
#define W_ 160
#define HW_ (H_ * W_)
#define N_ (D_ * H_ * W_)          // 4,915,200
#define R_ 4
#define WSZ 729.0f

#define HCHUNK 24                   // h rows per boxWH block
#define NHCH (H_ / HCHUNK)          // 8
#define NBLK_WH (D_ * NHCH)         // 1280
#define GBLK 768                    // grad blocks appended to kernel 1
#define TPB1 160

#define DCHUNK 16
#define GRID3X (HW_ / 256)          // 120
#define GRID3Y (D_ / DCHUNK)        // 10
#define NPART3 (GRID3X * GRID3Y)    // 1200

// Scratch (static device globals)
__device__ float g_B[5u * N_];      // W+H box-summed channels
__device__ float g_ccpart[NPART3];
__device__ float g_gpart[GBLK * 3];
__device__ unsigned int g_cnt;

// ---------------------------------------------------------------------------
// Kernel 1: blocks [0, NBLK_WH) fused W+H box-sum (products on the fly,
// 9-tap W sum via smem row, running H window via 9-row ring). Remaining
// GBLK blocks compute gradient-loss partials.
// ---------------------------------------------------------------------------
__global__ void __launch_bounds__(TPB1) k_A(const float* __restrict__ I,
                                            const float* __restrict__ J,
                                            const float* __restrict__ dsp)
{
    const int bid = blockIdx.x;
    const int w   = threadIdx.x;

    if (bid == 0 && w == 0) g_cnt = 0u;   // reset for graph replay

    if (bid < NBLK_WH) {
        __shared__ float ring[9][5][W_];
        __shared__ float sI[W_ + 2 * R_];
        __shared__ float sJ[W_ + 2 * R_];

        const int d  = bid / NHCH;
        const int h0 = (bid % NHCH) * HCHUNK;

        if (w < R_) {
            sI[w] = 0.f; sJ[w] = 0.f;
            sI[W_ + R_ + w] = 0.f; sJ[W_ + R_ + w] = 0.f;
        }

        const float* __restrict__ Ib = I + (size_t)d * HW_;
        const float* __restrict__ Jb = J + (size_t)d * HW_;

        float S0 = 0.f, S1 = 0.f, S2 = 0.f, S3 = 0.f, S4 = 0.f;

        for (int h = h0 - R_; h < h0 + HCHUNK + R_; h++) {
            __syncthreads();
            const bool valid = (h >= 0) & (h < H_);
            if (valid) {
                sI[w + R_] = Ib[h * W_ + w];
                sJ[w + R_] = Jb[h * W_ + w];
            }
            __syncthreads();

            float ws0 = 0.f, ws1 = 0.f, ws2 = 0.f, ws3 = 0.f, ws4 = 0.f;
            if (valid) {
#pragma unroll
                for (int k = 0; k < 2 * R_ + 1; k++) {
                    float a = sI[w + k];
                    float b = sJ[w + k];
                    ws0 += a; ws1 += b;
                    ws2 += a * a; ws3 += b * b; ws4 += a * b;
                }
            }
            const int slot = (h + 27) % 9;
            ring[slot][0][w] = ws0; S0 += ws0;
            ring[slot][1][w] = ws1; S1 += ws1;
            ring[slot][2][w] = ws2; S2 += ws2;
            ring[slot][3][w] = ws3; S3 += ws3;
            ring[slot][4][w] = ws4; S4 += ws4;

            const int ho = h - R_;
            if (ho >= h0 && ho < h0 + HCHUNK) {
                const size_t o = (size_t)d * HW_ + ho * W_ + w;
                g_B[0u * N_ + o] = S0;
                g_B[1u * N_ + o] = S1;
                g_B[2u * N_ + o] = S2;
                g_B[3u * N_ + o] = S3;
                g_B[4u * N_ + o] = S4;
            }
            const int hl = h - 2 * R_;
            if (hl >= h0 - R_) {
                const int ls = (hl + 27) % 9;
                S0 -= ring[ls][0][w];
                S1 -= ring[ls][1][w];
                S2 -= ring[ls][2][w];
                S3 -= ring[ls][3][w];
                S4 -= ring[ls][4][w];
            }
        }
    } else {
        // ----- gradient-loss partials (float4 vectorized) -----
        const int gid = bid - NBLK_WH;
        const int W4 = W_ / 4;
        const int NV = N_ / 4;
        const int total = 3 * NV;
        const float4* __restrict__ p4 = (const float4*)dsp;
        const float*  __restrict__ pf = dsp;

        float aH = 0.f, aD = 0.f, aW = 0.f;
        for (int i = gid * TPB1 + w; i < total; i += GBLK * TPB1) {
            const int r  = i % NV;
            const int wv = r % W4;
            const int h  = (r / W4) % H_;
            const int d  = r / (W4 * H_);

            const float4 v = p4[i];
            float t;
            t = v.y - v.x; aW += t * t;
            t = v.z - v.y; aW += t * t;
            t = v.w - v.z; aW += t * t;
            if (wv < W4 - 1) { t = pf[i * 4 + 4] - v.w; aW += t * t; }
            if (h < H_ - 1) {
                const float4 u = p4[i + W4];
                t = u.x - v.x; aH += t * t;
                t = u.y - v.y; aH += t * t;
                t = u.z - v.z; aH += t * t;
                t = u.w - v.w; aH += t * t;
            }
            if (d < D_ - 1) {
                const float4 u = p4[i + HW_ / 4];
                t = u.x - v.x; aD += t * t;
                t = u.y - v.y; aD += t * t;
                t = u.z - v.z; aD += t * t;
                t = u.w - v.w; aD += t * t;
            }
        }

        __shared__ float sh[3][TPB1];
        sh[0][w] = aH; sh[1][w] = aD; sh[2][w] = aW;
        __syncthreads();
        if (w < 80) { sh[0][w] += sh[0][w+80]; sh[1][w] += sh[1][w+80]; sh[2][w] += sh[2][w+80]; }
        __syncthreads();
        if (w < 40) { sh[0][w] += sh[0][w+40]; sh[1][w] += sh[1][w+40]; sh[2][w] += sh[2][w+40]; }
        __syncthreads();
        if (w < 20) { sh[0][w] += sh[0][w+20]; sh[1][w] += sh[1][w+20]; sh[2][w] += sh[2][w+20]; }
        __syncthreads();
        if (w < 10) { sh[0][w] += sh[0][w+10]; sh[1][w] += sh[1][w+10]; sh[2][w] += sh[2][w+10]; }
        __syncthreads();
        if (w < 5)  { sh[0][w] += sh[0][w+5];  sh[1][w] += sh[1][w+5];  sh[2][w] += sh[2][w+5];  }
        __syncthreads();
        if (w == 0) {
            g_gpart[gid * 3 + 0] = sh[0][0] + sh[0][1] + sh[0][2] + sh[0][3] + sh[0][4];
            g_gpart[gid * 3 + 1] = sh[1][0] + sh[1][1] + sh[1][2] + sh[1][3] + sh[1][4];
            g_gpart[gid * 3 + 2] = sh[2][0] + sh[2][1] + sh[2][2] + sh[2][3] + sh[2][4];
        }
    }
}

// ---------------------------------------------------------------------------
// Kernel 2: box-sum along D (running window) fused with cc formula +
// block reduction; last finishing block does the final combine.
// grid = (120, 10), block = 256.
// ---------------------------------------------------------------------------
__global__ void __launch_bounds__(256) k_B(float* __restrict__ out)
{
    const int hw = blockIdx.x * 256 + threadIdx.x;
    const int d0 = blockIdx.y * DCHUNK;

    float S[5];
#pragma unroll
    for (int c = 0; c < 5; c++) {
        const float* __restrict__ p = g_B + (size_t)c * N_ + hw;
        float s = 0.f;
#pragma unroll
        for (int dd = d0 - R_; dd < d0 + R_; dd++)
            if (dd >= 0 && dd < D_) s += p[dd * HW_];
        S[c] = s;
    }

    float acc = 0.f;
    for (int d = d0; d < d0 + DCHUNK; d++) {
        const int dn = d + R_;
        if (dn < D_) {
#pragma unroll
            for (int c = 0; c < 5; c++)
                S[c] += g_B[(size_t)c * N_ + dn * HW_ + hw];
        }
        const float uI = S[0] * (1.0f / WSZ);
        const float uJ = S[1] * (1.0f / WSZ);
        const float cross = S[4] - uJ * S[0] - uI * S[1] + uI * uJ * WSZ;
        const float Iv = S[2] - 2.0f * uI * S[0] + uI * uI * WSZ;
        const float Jv = S[3] - 2.0f * uJ * S[1] + uJ * uJ * WSZ;
        acc += cross * cross / (Iv * Jv + 1e-5f);

        const int dp = d - R_;
        if (dp >= 0) {
#pragma unroll
            for (int c = 0; c < 5; c++)
                S[c] -= g_B[(size_t)c * N_ + dp * HW_ + hw];
        }
    }

    __shared__ float sh[256];
    const int t = threadIdx.x;
    sh[t] = acc;
    __syncthreads();
#pragma unroll
    for (int s = 128; s > 0; s >>= 1) {
        if (t < s) sh[t] += sh[t + s];
        __syncthreads();
    }
    if (t == 0) g_ccpart[blockIdx.y * GRID3X + blockIdx.x] = sh[0];

    // ----- last-block final combine -----
    __shared__ bool is_last;
    if (t == 0) {
        __threadfence();
        is_last = (atomicAdd(&g_cnt, 1u) == NPART3 - 1);
    }
    __syncthreads();
    if (!is_last) return;

    float cc = 0.f;
    for (int i = t; i < NPART3; i += 256) cc += g_ccpart[i];

    const float invNH = 1.0f / (3.0f * D_ * (H_ - 1) * W_);
    const float invND = 1.0f / (3.0f * (D_ - 1) * H_ * W_);
    const float invNW = 1.0f / (3.0f * D_ * H_ * (W_ - 1));

    float g = 0.f;
    for (int i = t; i < GBLK; i += 256) {
        g += g_gpart[i * 3 + 0] * invNH
           + g_gpart[i * 3 + 1] * invND
           + g_gpart[i * 3 + 2] * invNW;
    }

    __shared__ float shg[256];
    sh[t] = cc;
    shg[t] = g;
    __syncthreads();
#pragma unroll
    for (int s = 128; s > 0; s >>= 1) {
        if (t < s) { sh[t] += sh[t + s]; shg[t] += shg[t + s]; }
        __syncthreads();
    }
    if (t == 0)
        out[0] = (1.0f - sh[0] / (float)N_) + 0.01f * (shg[0] / 3.0f);
}

extern "C" void kernel_launch(void* const* d_in, const int* in_sizes, int n_in,
                              void* d_out, int out_size)
{
    const float* I   = (const float*)d_in[0];
    const float* J   = (const float*)d_in[1];
    const float* dsp = (const float*)d_in[2];
    float* out = (float*)d_out;

    k_A<<<NBLK_WH + GBLK, TPB1>>>(I, J, dsp);
    k_B<<<dim3(GRID3X, GRID3Y), 256>>>(out);
}

// round 5
// speedup vs baseline: 1.8159x; 1.1141x over previous
#include <cuda_runtime.h>
#include <cuda_fp16.h>

#define D_ 160
#define H_ 192
#define W_ 160
#define HW_ (H_ * W_)
#define N_ (D_ * H_ * W_)          // 4,915,200
#define R_ 4
#define WSZ 729.0f

#define HCHUNK 16                   // h rows per boxWH block
#define NHCH (H_ / HCHUNK)          // 12
#define NBLK_WH (D_ * NHCH)         // 1920
#define GBLK 768                    // grad blocks appended to kernel 1
#define TPB1 160

#define DCHUNK 16
#define GRID3X (HW_ / 256)          // 120
#define GRID3Y (D_ / DCHUNK)        // 10
#define NPART3 (GRID3X * GRID3Y)    // 1200

// Scratch (static device globals) — W+H box sums stored in fp16 (values <= 81,
// no cancellation until the fp32 cc stage; see precision analysis).
__device__ __half g_Bh[5u * N_];
__device__ float g_ccpart[NPART3];
__device__ float g_gpart[GBLK * 3];
__device__ unsigned int g_cnt;

// ---------------------------------------------------------------------------
// Kernel 1: blocks [0, NBLK_WH) fused W+H box-sum (products on the fly,
// 9-tap W sum via smem row, running H window via 9-row fp32 ring); output
// converted to fp16. Remaining GBLK blocks compute gradient-loss partials.
// ---------------------------------------------------------------------------
__global__ void __launch_bounds__(TPB1) k_A(const float* __restrict__ I,
                                            const float* __restrict__ J,
                                            const float* __restrict__ dsp)
{
    const int bid = blockIdx.x;
    const int w   = threadIdx.x;

    if (bid == 0 && w == 0) g_cnt = 0u;   // reset for graph replay

    if (bid < NBLK_WH) {
        __shared__ float ring[9][5][W_];
        __shared__ float sI[W_ + 2 * R_];
        __shared__ float sJ[W_ + 2 * R_];

        const int d  = bid / NHCH;
        const int h0 = (bid % NHCH) * HCHUNK;

        if (w < R_) {
            sI[w] = 0.f; sJ[w] = 0.f;
            sI[W_ + R_ + w] = 0.f; sJ[W_ + R_ + w] = 0.f;
        }

        const float* __restrict__ Ib = I + (size_t)d * HW_;
        const float* __restrict__ Jb = J + (size_t)d * HW_;

        float S0 = 0.f, S1 = 0.f, S2 = 0.f, S3 = 0.f, S4 = 0.f;

        for (int h = h0 - R_; h < h0 + HCHUNK + R_; h++) {
            __syncthreads();
            const bool valid = (h >= 0) & (h < H_);
            if (valid) {
                sI[w + R_] = Ib[h * W_ + w];
                sJ[w + R_] = Jb[h * W_ + w];
            }
            __syncthreads();

            float ws0 = 0.f, ws1 = 0.f, ws2 = 0.f, ws3 = 0.f, ws4 = 0.f;
            if (valid) {
#pragma unroll
                for (int k = 0; k < 2 * R_ + 1; k++) {
                    float a = sI[w + k];
                    float b = sJ[w + k];
                    ws0 += a; ws1 += b;
                    ws2 += a * a; ws3 += b * b; ws4 += a * b;
                }
            }
            const int slot = (h + 27) % 9;
            ring[slot][0][w] = ws0; S0 += ws0;
            ring[slot][1][w] = ws1; S1 += ws1;
            ring[slot][2][w] = ws2; S2 += ws2;
            ring[slot][3][w] = ws3; S3 += ws3;
            ring[slot][4][w] = ws4; S4 += ws4;

            const int ho = h - R_;
            if (ho >= h0 && ho < h0 + HCHUNK) {
                const size_t o = (size_t)d * HW_ + ho * W_ + w;
                g_Bh[0u * N_ + o] = __float2half_rn(S0);
                g_Bh[1u * N_ + o] = __float2half_rn(S1);
                g_Bh[2u * N_ + o] = __float2half_rn(S2);
                g_Bh[3u * N_ + o] = __float2half_rn(S3);
                g_Bh[4u * N_ + o] = __float2half_rn(S4);
            }
            const int hl = h - 2 * R_;
            if (hl >= h0 - R_) {
                const int ls = (hl + 27) % 9;
                S0 -= ring[ls][0][w];
                S1 -= ring[ls][1][w];
                S2 -= ring[ls][2][w];
                S3 -= ring[ls][3][w];
                S4 -= ring[ls][4][w];
            }
        }
    } else {
        // ----- gradient-loss partials (float4 vectorized) -----
        const int gid = bid - NBLK_WH;
        const int W4 = W_ / 4;
        const int NV = N_ / 4;
        const int total = 3 * NV;
        const float4* __restrict__ p4 = (const float4*)dsp;
        const float*  __restrict__ pf = dsp;

        float aH = 0.f, aD = 0.f, aW = 0.f;
        for (int i = gid * TPB1 + w; i < total; i += GBLK * TPB1) {
            const int r  = i % NV;
            const int wv = r % W4;
            const int h  = (r / W4) % H_;
            const int d  = r / (W4 * H_);

            const float4 v = p4[i];
            float t;
            t = v.y - v.x; aW += t * t;
            t = v.z - v.y; aW += t * t;
            t = v.w - v.z; aW += t * t;
            if (wv < W4 - 1) { t = pf[i * 4 + 4] - v.w; aW += t * t; }
            if (h < H_ - 1) {
                const float4 u = p4[i + W4];
                t = u.x - v.x; aH += t * t;
                t = u.y - v.y; aH += t * t;
                t = u.z - v.z; aH += t * t;
                t = u.w - v.w; aH += t * t;
            }
            if (d < D_ - 1) {
                const float4 u = p4[i + HW_ / 4];
                t = u.x - v.x; aD += t * t;
                t = u.y - v.y; aD += t * t;
                t = u.z - v.z; aD += t * t;
                t = u.w - v.w; aD += t * t;
            }
        }

        __shared__ float sh[3][TPB1];
        sh[0][w] = aH; sh[1][w] = aD; sh[2][w] = aW;
        __syncthreads();
        if (w < 80) { sh[0][w] += sh[0][w+80]; sh[1][w] += sh[1][w+80]; sh[2][w] += sh[2][w+80]; }
        __syncthreads();
        if (w < 40) { sh[0][w] += sh[0][w+40]; sh[1][w] += sh[1][w+40]; sh[2][w] += sh[2][w+40]; }
        __syncthreads();
        if (w < 20) { sh[0][w] += sh[0][w+20]; sh[1][w] += sh[1][w+20]; sh[2][w] += sh[2][w+20]; }
        __syncthreads();
        if (w < 10) { sh[0][w] += sh[0][w+10]; sh[1][w] += sh[1][w+10]; sh[2][w] += sh[2][w+10]; }
        __syncthreads();
        if (w < 5)  { sh[0][w] += sh[0][w+5];  sh[1][w] += sh[1][w+5];  sh[2][w] += sh[2][w+5];  }
        __syncthreads();
        if (w == 0) {
            g_gpart[gid * 3 + 0] = sh[0][0] + sh[0][1] + sh[0][2] + sh[0][3] + sh[0][4];
            g_gpart[gid * 3 + 1] = sh[1][0] + sh[1][1] + sh[1][2] + sh[1][3] + sh[1][4];
            g_gpart[gid * 3 + 2] = sh[2][0] + sh[2][1] + sh[2][2] + sh[2][3] + sh[2][4];
        }
    }
}

// ---------------------------------------------------------------------------
// Kernel 2: box-sum along D (running window, fp32 accum over fp16 scratch)
// fused with cc formula + block reduction; last block does final combine.
// ---------------------------------------------------------------------------
__global__ void __launch_bounds__(256) k_B(float* __restrict__ out)
{
    const int hw = blockIdx.x * 256 + threadIdx.x;
    const int d0 = blockIdx.y * DCHUNK;

    float S[5];
#pragma unroll
    for (int c = 0; c < 5; c++) {
        const __half* __restrict__ p = g_Bh + (size_t)c * N_ + hw;
        float s = 0.f;
#pragma unroll
        for (int dd = d0 - R_; dd < d0 + R_; dd++)
            if (dd >= 0 && dd < D_) s += __half2float(p[dd * HW_]);
        S[c] = s;
    }

    float acc = 0.f;
    for (int d = d0; d < d0 + DCHUNK; d++) {
        const int dn = d + R_;
        if (dn < D_) {
#pragma unroll
            for (int c = 0; c < 5; c++)
                S[c] += __half2float(g_Bh[(size_t)c * N_ + dn * HW_ + hw]);
        }
        const float uI = S[0] * (1.0f / WSZ);
        const float uJ = S[1] * (1.0f / WSZ);
        const float cross = S[4] - uJ * S[0] - uI * S[1] + uI * uJ * WSZ;
        const float Iv = S[2] - 2.0f * uI * S[0] + uI * uI * WSZ;
        const float Jv = S[3] - 2.0f * uJ * S[1] + uJ * uJ * WSZ;
        acc += cross * cross / (Iv * Jv + 1e-5f);

        const int dp = d - R_;
        if (dp >= 0) {
#pragma unroll
            for (int c = 0; c < 5; c++)
                S[c] -= __half2float(g_Bh[(size_t)c * N_ + dp * HW_ + hw]);
        }
    }

    __shared__ float sh[256];
    const int t = threadIdx.x;
    sh[t] = acc;
    __syncthreads();
#pragma unroll
    for (int s = 128; s > 0; s >>= 1) {
        if (t < s) sh[t] += sh[t + s];
        __syncthreads();
    }
    if (t == 0) g_ccpart[blockIdx.y * GRID3X + blockIdx.x] = sh[0];

    // ----- last-block final combine -----
    __shared__ bool is_last;
    if (t == 0) {
        __threadfence();
        is_last = (atomicAdd(&g_cnt, 1u) == NPART3 - 1);
    }
    __syncthreads();
    if (!is_last) return;

    float cc = 0.f;
    for (int i = t; i < NPART3; i += 256) cc += g_ccpart[i];

    const float invNH = 1.0f / (3.0f * D_ * (H_ - 1) * W_);
    const float invND = 1.0f / (3.0f * (D_ - 1) * H_ * W_);
    const float invNW = 1.0f / (3.0f * D_ * H_ * (W_ - 1));

    float g = 0.f;
    for (int i = t; i < GBLK; i += 256) {
        g += g_gpart[i * 3 + 0] * invNH
           + g_gpart[i * 3 + 1] * invND
           + g_gpart[i * 3 + 2] * invNW;
    }

    __shared__ float shg[256];
    sh[t] = cc;
    shg[t] = g;
    __syncthreads();
#pragma unroll
    for (int s = 128; s > 0; s >>= 1) {
        if (t < s) { sh[t] += sh[t + s]; shg[t] += shg[t + s]; }
        __syncthreads();
    }
    if (t == 0)
        out[0] = (1.0f - sh[0] / (float)N_) + 0.01f * (shg[0] / 3.0f);
}

extern "C" void kernel_launch(void* const* d_in, const int* in_sizes, int n_in,
                              void* d_out, int out_size)
{
    const float* I   = (const float*)d_in[0];
    const float* J   = (const float*)d_in[1];
    const float* dsp = (const float*)d_in[2];
    float* out = (float*)d_out;

    k_A<<<NBLK_WH + GBLK, TPB1>>>(I, J, dsp);
    k_B<<<dim3(GRID3X, GRID3Y), 256>>>(out);
}

// round 6
// speedup vs baseline: 2.2367x; 1.2317x over previous
#include <cuda_runtime.h>
#include <cuda_fp16.h>

#define D_ 160
#define H_ 192
#define W_ 160
#define HW_ (H_ * W_)
#define N_ (D_ * H_ * W_)          // 4,915,200
#define R_ 4
#define WSZ 729.0f

#define HCHUNK 16                   // h rows per boxWH block
#define NHCH (H_ / HCHUNK)          // 12
#define NBLK_WH (D_ * NHCH)         // 1920
#define GBLK 768                    // grad blocks appended to kernel 1
#define TPB1 160

#define DCHUNK 8
#define HW2 (HW_ / 2)               // 15360 half2 positions per slice
#define GRID3X (HW2 / 512)          // 30
#define GRID3Y (D_ / DCHUNK)        // 20
#define NPART3 (GRID3X * GRID3Y)    // 600

// Scratch — W+H box sums in fp16 (values <= 81; cancellation-heavy math stays fp32)
__device__ __half g_Bh[5u * N_];
__device__ float g_ccpart[NPART3];
__device__ float g_gpart[GBLK * 3];
__device__ unsigned int g_cnt;

// ---------------------------------------------------------------------------
// Kernel 1: blocks [0, NBLK_WH): fused W+H box-sum. Ping-pong row buffers
// (one sync/row, prefetched gmem), fp16 ring for the 9-row H window.
// Blocks [NBLK_WH, +GBLK): gradient-loss partials.
// ---------------------------------------------------------------------------
__global__ void __launch_bounds__(TPB1) k_A(const float* __restrict__ I,
                                            const float* __restrict__ J,
                                            const float* __restrict__ dsp)
{
    const int bid = blockIdx.x;
    const int w   = threadIdx.x;

    if (bid == 0 && w == 0) g_cnt = 0u;   // reset for graph replay

    if (bid < NBLK_WH) {
        __shared__ float  bufI[2][W_ + 2 * R_];
        __shared__ float  bufJ[2][W_ + 2 * R_];
        __shared__ __half ring[9][5][W_];

        const int d  = bid / NHCH;
        const int h0 = (bid % NHCH) * HCHUNK;

        if (w < R_) {
#pragma unroll
            for (int b = 0; b < 2; b++) {
                bufI[b][w] = 0.f; bufJ[b][w] = 0.f;
                bufI[b][W_ + R_ + w] = 0.f; bufJ[b][W_ + R_ + w] = 0.f;
            }
        }

        const float* __restrict__ Ib = I + (size_t)d * HW_;
        const float* __restrict__ Jb = J + (size_t)d * HW_;

        float S0 = 0.f, S1 = 0.f, S2 = 0.f, S3 = 0.f, S4 = 0.f;

        // preload first row (h0-R) into buffer 0
        {
            const int h = h0 - R_;
            float a = 0.f, b = 0.f;
            if (h >= 0) { a = Ib[h * W_ + w]; b = Jb[h * W_ + w]; }
            bufI[0][w + R_] = a;
            bufJ[0][w + R_] = b;
        }
        __syncthreads();

        int cur = 0;
        for (int h = h0 - R_; h < h0 + HCHUNK + R_; h++) {
            // prefetch next row into registers (no dependence on smem)
            float nI = 0.f, nJ = 0.f;
            const int hn = h + 1;
            if (hn >= 0 && hn < H_ && hn < h0 + HCHUNK + R_) {
                nI = Ib[hn * W_ + w];
                nJ = Jb[hn * W_ + w];
            }

            // 9-tap W box sums from current buffer
            float ws0 = 0.f, ws1 = 0.f, ws2 = 0.f, ws3 = 0.f, ws4 = 0.f;
#pragma unroll
            for (int k = 0; k < 2 * R_ + 1; k++) {
                float a = bufI[cur][w + k];
                float b = bufJ[cur][w + k];
                ws0 += a; ws1 += b;
                ws2 += a * a; ws3 += b * b; ws4 += a * b;
            }

            // round once; add & later subtract the identical rounded value
            const __half q0 = __float2half_rn(ws0);
            const __half q1 = __float2half_rn(ws1);
            const __half q2 = __float2half_rn(ws2);
            const __half q3 = __float2half_rn(ws3);
            const __half q4 = __float2half_rn(ws4);
            const int slot = (h + 27) % 9;
            ring[slot][0][w] = q0; S0 += __half2float(q0);
            ring[slot][1][w] = q1; S1 += __half2float(q1);
            ring[slot][2][w] = q2; S2 += __half2float(q2);
            ring[slot][3][w] = q3; S3 += __half2float(q3);
            ring[slot][4][w] = q4; S4 += __half2float(q4);

            const int ho = h - R_;
            if (ho >= h0 && ho < h0 + HCHUNK) {
                const size_t o = (size_t)d * HW_ + ho * W_ + w;
                g_Bh[0u * N_ + o] = __float2half_rn(S0);
                g_Bh[1u * N_ + o] = __float2half_rn(S1);
                g_Bh[2u * N_ + o] = __float2half_rn(S2);
                g_Bh[3u * N_ + o] = __float2half_rn(S3);
                g_Bh[4u * N_ + o] = __float2half_rn(S4);
            }
            const int hl = h - 2 * R_;
            if (hl >= h0 - R_) {
                const int ls = (hl + 27) % 9;
                S0 -= __half2float(ring[ls][0][w]);
                S1 -= __half2float(ring[ls][1][w]);
                S2 -= __half2float(ring[ls][2][w]);
                S3 -= __half2float(ring[ls][3][w]);
                S4 -= __half2float(ring[ls][4][w]);
            }

            // stage next row into the other buffer; single sync per row
            bufI[cur ^ 1][w + R_] = nI;
            bufJ[cur ^ 1][w + R_] = nJ;
            __syncthreads();
            cur ^= 1;
        }
    } else {
        // ----- gradient-loss partials (float4 vectorized) -----
        const int gid = bid - NBLK_WH;
        const int W4 = W_ / 4;
        const int NV = N_ / 4;
        const int total = 3 * NV;
        const float4* __restrict__ p4 = (const float4*)dsp;
        const float*  __restrict__ pf = dsp;

        float aH = 0.f, aD = 0.f, aW = 0.f;
        for (int i = gid * TPB1 + w; i < total; i += GBLK * TPB1) {
            const int r  = i % NV;
            const int wv = r % W4;
            const int h  = (r / W4) % H_;
            const int d  = r / (W4 * H_);

            const float4 v = p4[i];
            float t;
            t = v.y - v.x; aW += t * t;
            t = v.z - v.y; aW += t * t;
            t = v.w - v.z; aW += t * t;
            if (wv < W4 - 1) { t = pf[i * 4 + 4] - v.w; aW += t * t; }
            if (h < H_ - 1) {
                const float4 u = p4[i + W4];
                t = u.x - v.x; aH += t * t;
                t = u.y - v.y; aH += t * t;
                t = u.z - v.z; aH += t * t;
                t = u.w - v.w; aH += t * t;
            }
            if (d < D_ - 1) {
                const float4 u = p4[i + HW_ / 4];
                t = u.x - v.x; aD += t * t;
                t = u.y - v.y; aD += t * t;
                t = u.z - v.z; aD += t * t;
                t = u.w - v.w; aD += t * t;
            }
        }

        __shared__ float sh[3][TPB1];
        sh[0][w] = aH; sh[1][w] = aD; sh[2][w] = aW;
        __syncthreads();
        if (w < 80) { sh[0][w] += sh[0][w+80]; sh[1][w] += sh[1][w+80]; sh[2][w] += sh[2][w+80]; }
        __syncthreads();
        if (w < 40) { sh[0][w] += sh[0][w+40]; sh[1][w] += sh[1][w+40]; sh[2][w] += sh[2][w+40]; }
        __syncthreads();
        if (w < 20) { sh[0][w] += sh[0][w+20]; sh[1][w] += sh[1][w+20]; sh[2][w] += sh[2][w+20]; }
        __syncthreads();
        if (w < 10) { sh[0][w] += sh[0][w+10]; sh[1][w] += sh[1][w+10]; sh[2][w] += sh[2][w+10]; }
        __syncthreads();
        if (w < 5)  { sh[0][w] += sh[0][w+5];  sh[1][w] += sh[1][w+5];  sh[2][w] += sh[2][w+5];  }
        __syncthreads();
        if (w == 0) {
            g_gpart[gid * 3 + 0] = sh[0][0] + sh[0][1] + sh[0][2] + sh[0][3] + sh[0][4];
            g_gpart[gid * 3 + 1] = sh[1][0] + sh[1][1] + sh[1][2] + sh[1][3] + sh[1][4];
            g_gpart[gid * 3 + 2] = sh[2][0] + sh[2][1] + sh[2][2] + sh[2][3] + sh[2][4];
        }
    }
}

// ---------------------------------------------------------------------------
// Kernel 2: D-axis running box sum over half2 (2 voxels/thread) fused with
// the cc formula + block reduction; last finishing block does final combine.
// grid = (30, 20), block = 512.
// ---------------------------------------------------------------------------
__global__ void __launch_bounds__(512) k_B(float* __restrict__ out)
{
    const int t = threadIdx.x;
    const int p  = blockIdx.x * 512 + t;     // half2 position in a slice
    const int d0 = blockIdx.y * DCHUNK;

    const __half2* __restrict__ P0 = (const __half2*)(g_Bh + 0u * N_);
    const __half2* __restrict__ P1 = (const __half2*)(g_Bh + 1u * N_);
    const __half2* __restrict__ P2 = (const __half2*)(g_Bh + 2u * N_);
    const __half2* __restrict__ P3 = (const __half2*)(g_Bh + 3u * N_);
    const __half2* __restrict__ P4 = (const __half2*)(g_Bh + 4u * N_);

    float2 S0 = {0.f, 0.f}, S1 = {0.f, 0.f}, S2 = {0.f, 0.f},
           S3 = {0.f, 0.f}, S4 = {0.f, 0.f};

#pragma unroll
    for (int dd = d0 - R_; dd < d0 + R_; dd++) {
        if (dd >= 0 && dd < D_) {
            const int o = dd * HW2 + p;
            float2 v;
            v = __half22float2(P0[o]); S0.x += v.x; S0.y += v.y;
            v = __half22float2(P1[o]); S1.x += v.x; S1.y += v.y;
            v = __half22float2(P2[o]); S2.x += v.x; S2.y += v.y;
            v = __half22float2(P3[o]); S3.x += v.x; S3.y += v.y;
            v = __half22float2(P4[o]); S4.x += v.x; S4.y += v.y;
        }
    }

    float acc = 0.f;
    for (int d = d0; d < d0 + DCHUNK; d++) {
        const int dn = d + R_;
        if (dn < D_) {
            const int o = dn * HW2 + p;
            float2 v;
            v = __half22float2(P0[o]); S0.x += v.x; S0.y += v.y;
            v = __half22float2(P1[o]); S1.x += v.x; S1.y += v.y;
            v = __half22float2(P2[o]); S2.x += v.x; S2.y += v.y;
            v = __half22float2(P3[o]); S3.x += v.x; S3.y += v.y;
            v = __half22float2(P4[o]); S4.x += v.x; S4.y += v.y;
        }
        {
            const float uI = S0.x * (1.0f / WSZ);
            const float uJ = S1.x * (1.0f / WSZ);
            const float cross = S4.x - uJ * S0.x - uI * S1.x + uI * uJ * WSZ;
            const float Iv = S2.x - 2.0f * uI * S0.x + uI * uI * WSZ;
            const float Jv = S3.x - 2.0f * uJ * S1.x + uJ * uJ * WSZ;
            acc += cross * cross / (Iv * Jv + 1e-5f);
        }
        {
            const float uI = S0.y * (1.0f / WSZ);
            const float uJ = S1.y * (1.0f / WSZ);
            const float cross = S4.y - uJ * S0.y - uI * S1.y + uI * uJ * WSZ;
            const float Iv = S2.y - 2.0f * uI * S0.y + uI * uI * WSZ;
            const float Jv = S3.y - 2.0f * uJ * S1.y + uJ * uJ * WSZ;
            acc += cross * cross / (Iv * Jv + 1e-5f);
        }
        const int dp = d - R_;
        if (dp >= 0) {
            const int o = dp * HW2 + p;
            float2 v;
            v = __half22float2(P0[o]); S0.x -= v.x; S0.y -= v.y;
            v = __half22float2(P1[o]); S1.x -= v.x; S1.y -= v.y;
            v = __half22float2(P2[o]); S2.x -= v.x; S2.y -= v.y;
            v = __half22float2(P3[o]); S3.x -= v.x; S3.y -= v.y;
            v = __half22float2(P4[o]); S4.x -= v.x; S4.y -= v.y;
        }
    }

    __shared__ float sh[512];
    sh[t] = acc;
    __syncthreads();
#pragma unroll
    for (int s = 256; s > 0; s >>= 1) {
        if (t < s) sh[t] += sh[t + s];
        __syncthreads();
    }
    if (t == 0) g_ccpart[blockIdx.y * GRID3X + blockIdx.x] = sh[0];

    // ----- last-block final combine -----
    __shared__ bool is_last;
    if (t == 0) {
        __threadfence();
        is_last = (atomicAdd(&g_cnt, 1u) == NPART3 - 1);
    }
    __syncthreads();
    if (!is_last) return;

    float cc = 0.f;
    for (int i = t; i < NPART3; i += 512) cc += g_ccpart[i];

    const float invNH = 1.0f / (3.0f * D_ * (H_ - 1) * W_);
    const float invND = 1.0f / (3.0f * (D_ - 1) * H_ * W_);
    const float invNW = 1.0f / (3.0f * D_ * H_ * (W_ - 1));

    float g = 0.f;
    for (int i = t; i < GBLK; i += 512) {
        g += g_gpart[i * 3 + 0] * invNH
           + g_gpart[i * 3 + 1] * invND
           + g_gpart[i * 3 + 2] * invNW;
    }

    __shared__ float shg[512];
    sh[t] = cc;
    shg[t] = g;
    __syncthreads();
#pragma unroll
    for (int s = 256; s > 0; s >>= 1) {
        if (t < s) { sh[t] += sh[t + s]; shg[t] += shg[t + s]; }
        __syncthreads();
    }
    if (t == 0)
        out[0] = (1.0f - sh[0] / (float)N_) + 0.01f * (shg[0] / 3.0f);
}

extern "C" void kernel_launch(void* const* d_in, const int* in_sizes, int n_in,
                              void* d_out, int out_size)
{
    const float* I   = (const float*)d_in[0];
    const float* J   = (const float*)d_in[1];
    const float* dsp = (const float*)d_in[2];
    float* out = (float*)d_out;

    k_A<<<NBLK_WH + GBLK, TPB1>>>(I, J, dsp);
    k_B<<<dim3(GRID3X, GRID3Y), 512>>>(out);
}

// round 7
// speedup vs baseline: 2.3379x; 1.0452x over previous
#include <cuda_runtime.h>
#include <cuda_fp16.h>

#define D_ 160
#define H_ 192
#define W_ 160
#define HW_ (H_ * W_)
#define N_ (D_ * H_ * W_)          // 4,915,200
#define R_ 4
#define WSZ 729.0f

#define W2 (W_ / 2)                 // 80 half2/float2 lanes per row
#define HSUB 16                     // output rows per 80-lane group
#define NHCH (H_ / (2 * HSUB))      // 6 (each block = 2 groups = 32 rows)
#define NBLK_WH (D_ * NHCH)         // 960
#define GBLK 768
#define TPB1 160

#define DCHUNK 8
#define HW4 (HW_ / 4)               // 7680 4-voxel positions per slice
#define GRID3X (HW4 / 512)          // 15
#define GRID3Y (D_ / DCHUNK)        // 20
#define NPART3 (GRID3X * GRID3Y)    // 300

// Scratch — W+H box sums in fp16 (values <= 81; cancellation-heavy math stays fp32)
__device__ __half g_Bh[5u * N_];
__device__ float g_ccpart[NPART3];
__device__ float g_gpart[GBLK * 3];
__device__ unsigned int g_cnt;

__device__ __forceinline__ float ccf(float s0, float s1, float s2, float s3, float s4)
{
    const float uI = s0 * (1.0f / WSZ);
    const float uJ = s1 * (1.0f / WSZ);
    const float cross = s4 - uJ * s0 - uI * s1 + uI * uJ * WSZ;
    const float Iv = s2 - 2.0f * uI * s0 + uI * uI * WSZ;
    const float Jv = s3 - 2.0f * uJ * s1 + uJ * uJ * WSZ;
    return cross * cross / (Iv * Jv + 1e-5f);
}

// ---------------------------------------------------------------------------
// Kernel 1, blocks [0, NBLK_WH): fused W+H box-sum, 2 voxels/thread.
// 160 threads = 2 groups x 80 lanes; each group owns an HSUB-row subchunk.
// Ping-pong float2 row buffers (1 sync/row), fp16 half2 ring for H window.
// Blocks [NBLK_WH, +GBLK): gradient-loss partials.
// ---------------------------------------------------------------------------
__global__ void __launch_bounds__(TPB1) k_A(const float* __restrict__ I,
                                            const float* __restrict__ J,
                                            const float* __restrict__ dsp)
{
    const int bid = blockIdx.x;
    const int tid = threadIdx.x;

    if (bid == 0 && tid == 0) g_cnt = 0u;   // reset for graph replay

    if (bid < NBLK_WH) {
        __shared__ float2  bI[2][2][W2 + 4];   // [group][pp][cell]
        __shared__ float2  bJ[2][2][W2 + 4];
        __shared__ __half2 ring[2][9][5][W2];

        const int g    = tid / W2;             // 0 or 1
        const int lane = tid % W2;             // 0..79
        const int d    = bid / NHCH;
        const int hg0  = (bid % NHCH) * (2 * HSUB) + g * HSUB;

        if (lane < 2) {
#pragma unroll
            for (int pp = 0; pp < 2; pp++) {
                bI[g][pp][lane] = make_float2(0.f, 0.f);
                bI[g][pp][W2 + 2 + lane] = make_float2(0.f, 0.f);
                bJ[g][pp][lane] = make_float2(0.f, 0.f);
                bJ[g][pp][W2 + 2 + lane] = make_float2(0.f, 0.f);
            }
        }

        const float2* __restrict__ I2p = (const float2*)(I + (size_t)d * HW_);
        const float2* __restrict__ J2p = (const float2*)(J + (size_t)d * HW_);

        float2 S0 = {0.f,0.f}, S1 = {0.f,0.f}, S2 = {0.f,0.f},
               S3 = {0.f,0.f}, S4 = {0.f,0.f};

        {   // preload first row (hg0-R) into pp buffer 0
            const int h = hg0 - R_;
            float2 a = {0.f,0.f}, b = {0.f,0.f};
            if (h >= 0) { a = I2p[h * W2 + lane]; b = J2p[h * W2 + lane]; }
            bI[g][0][lane + 2] = a;
            bJ[g][0][lane + 2] = b;
        }
        __syncthreads();

        int cur = 0;
        for (int h = hg0 - R_; h < hg0 + HSUB + R_; h++) {
            // prefetch next row
            float2 nI = {0.f,0.f}, nJ = {0.f,0.f};
            const int hn = h + 1;
            if (hn >= 0 && hn < H_) {
                nI = I2p[hn * W2 + lane];
                nJ = J2p[hn * W2 + lane];
            }

            // gather 10 input values per array (5 aligned float2 cells)
            float vI[10], vJ[10];
#pragma unroll
            for (int j = 0; j < 5; j++) {
                const float2 cI = bI[g][cur][lane + j];
                const float2 cJ = bJ[g][cur][lane + j];
                vI[2*j] = cI.x; vI[2*j+1] = cI.y;
                vJ[2*j] = cJ.x; vJ[2*j+1] = cJ.y;
            }

            // even output = taps 0..8; odd = even - ch(0) + ch(9)
            float e0=0.f,e1=0.f,e2=0.f,e3=0.f,e4=0.f;
#pragma unroll
            for (int i = 0; i < 9; i++) {
                const float a = vI[i], b = vJ[i];
                e0 += a; e1 += b; e2 += a*a; e3 += b*b; e4 += a*b;
            }
            const float o0 = e0 - vI[0] + vI[9];
            const float o1 = e1 - vJ[0] + vJ[9];
            const float o2 = e2 - vI[0]*vI[0] + vI[9]*vI[9];
            const float o3 = e3 - vJ[0]*vJ[0] + vJ[9]*vJ[9];
            const float o4 = e4 - vI[0]*vJ[0] + vI[9]*vJ[9];

            // quantize once; add & subtract the identical rounded value
            const __half2 q0 = __floats2half2_rn(e0, o0);
            const __half2 q1 = __floats2half2_rn(e1, o1);
            const __half2 q2 = __floats2half2_rn(e2, o2);
            const __half2 q3 = __floats2half2_rn(e3, o3);
            const __half2 q4 = __floats2half2_rn(e4, o4);
            const int slot = (h + 27) % 9;
            float2 f;
            ring[g][slot][0][lane] = q0; f = __half22float2(q0); S0.x += f.x; S0.y += f.y;
            ring[g][slot][1][lane] = q1; f = __half22float2(q1); S1.x += f.x; S1.y += f.y;
            ring[g][slot][2][lane] = q2; f = __half22float2(q2); S2.x += f.x; S2.y += f.y;
            ring[g][slot][3][lane] = q3; f = __half22float2(q3); S3.x += f.x; S3.y += f.y;
            ring[g][slot][4][lane] = q4; f = __half22float2(q4); S4.x += f.x; S4.y += f.y;

            const int ho = h - R_;
            if (ho >= hg0 && ho < hg0 + HSUB) {
                const size_t ob = ((size_t)d * HW_ + (size_t)ho * W_) >> 1;
                __half2* __restrict__ o = (__half2*)g_Bh;
                o[(0u*N_>>1) + ob + lane] = __floats2half2_rn(S0.x, S0.y);
                o[(1u*N_>>1) + ob + lane] = __floats2half2_rn(S1.x, S1.y);
                o[(2u*N_>>1) + ob + lane] = __floats2half2_rn(S2.x, S2.y);
                o[(3u*N_>>1) + ob + lane] = __floats2half2_rn(S3.x, S3.y);
                o[(4u*N_>>1) + ob + lane] = __floats2half2_rn(S4.x, S4.y);
            }
            const int hl = h - 2 * R_;
            if (hl >= hg0 - R_) {
                const int ls = (hl + 27) % 9;
                f = __half22float2(ring[g][ls][0][lane]); S0.x -= f.x; S0.y -= f.y;
                f = __half22float2(ring[g][ls][1][lane]); S1.x -= f.x; S1.y -= f.y;
                f = __half22float2(ring[g][ls][2][lane]); S2.x -= f.x; S2.y -= f.y;
                f = __half22float2(ring[g][ls][3][lane]); S3.x -= f.x; S3.y -= f.y;
                f = __half22float2(ring[g][ls][4][lane]); S4.x -= f.x; S4.y -= f.y;
            }

            bI[g][cur ^ 1][lane + 2] = nI;
            bJ[g][cur ^ 1][lane + 2] = nJ;
            __syncthreads();
            cur ^= 1;
        }
    } else {
        // ----- gradient-loss partials (float4 vectorized) -----
        const int gid = bid - NBLK_WH;
        const int W4 = W_ / 4;
        const int NV = N_ / 4;
        const int total = 3 * NV;
        const float4* __restrict__ p4 = (const float4*)dsp;
        const float*  __restrict__ pf = dsp;
        const int w = tid;

        float aH = 0.f, aD = 0.f, aW = 0.f;
        for (int i = gid * TPB1 + w; i < total; i += GBLK * TPB1) {
            const int r  = i % NV;
            const int wv = r % W4;
            const int h  = (r / W4) % H_;
            const int d  = r / (W4 * H_);

            const float4 v = p4[i];
            float t;
            t = v.y - v.x; aW += t * t;
            t = v.z - v.y; aW += t * t;
            t = v.w - v.z; aW += t * t;
            if (wv < W4 - 1) { t = pf[i * 4 + 4] - v.w; aW += t * t; }
            if (h < H_ - 1) {
                const float4 u = p4[i + W4];
                t = u.x - v.x; aH += t * t;
                t = u.y - v.y; aH += t * t;
                t = u.z - v.z; aH += t * t;
                t = u.w - v.w; aH += t * t;
            }
            if (d < D_ - 1) {
                const float4 u = p4[i + HW_ / 4];
                t = u.x - v.x; aD += t * t;
                t = u.y - v.y; aD += t * t;
                t = u.z - v.z; aD += t * t;
                t = u.w - v.w; aD += t * t;
            }
        }

        __shared__ float sh[3][TPB1];
        sh[0][w] = aH; sh[1][w] = aD; sh[2][w] = aW;
        __syncthreads();
        if (w < 80) { sh[0][w] += sh[0][w+80]; sh[1][w] += sh[1][w+80]; sh[2][w] += sh[2][w+80]; }
        __syncthreads();
        if (w < 40) { sh[0][w] += sh[0][w+40]; sh[1][w] += sh[1][w+40]; sh[2][w] += sh[2][w+40]; }
        __syncthreads();
        if (w < 20) { sh[0][w] += sh[0][w+20]; sh[1][w] += sh[1][w+20]; sh[2][w] += sh[2][w+20]; }
        __syncthreads();
        if (w < 10) { sh[0][w] += sh[0][w+10]; sh[1][w] += sh[1][w+10]; sh[2][w] += sh[2][w+10]; }
        __syncthreads();
        if (w < 5)  { sh[0][w] += sh[0][w+5];  sh[1][w] += sh[1][w+5];  sh[2][w] += sh[2][w+5];  }
        __syncthreads();
        if (w == 0) {
            g_gpart[gid * 3 + 0] = sh[0][0] + sh[0][1] + sh[0][2] + sh[0][3] + sh[0][4];
            g_gpart[gid * 3 + 1] = sh[1][0] + sh[1][1] + sh[1][2] + sh[1][3] + sh[1][4];
            g_gpart[gid * 3 + 2] = sh[2][0] + sh[2][1] + sh[2][2] + sh[2][3] + sh[2][4];
        }
    }
}

// ---------------------------------------------------------------------------
// Kernel 2: D-axis running box sum, 4 voxels/thread (8-byte fp16 loads),
// fused with cc formula + block reduction; last block does final combine.
// grid = (15, 20), block = 512.
// ---------------------------------------------------------------------------
__device__ __forceinline__ float4 ld4h(const float2* __restrict__ P, int idx)
{
    float2 r = P[idx];
    const __half2 a = *reinterpret_cast<const __half2*>(&r.x);
    const __half2 b = *reinterpret_cast<const __half2*>(&r.y);
    const float2 fa = __half22float2(a);
    const float2 fb = __half22float2(b);
    return make_float4(fa.x, fa.y, fb.x, fb.y);
}

__global__ void __launch_bounds__(512) k_B(float* __restrict__ out)
{
    const int t = threadIdx.x;
    const int q  = blockIdx.x * 512 + t;     // 4-voxel position in a slice
    const int d0 = blockIdx.y * DCHUNK;

    const float2* __restrict__ P0 = (const float2*)(g_Bh + 0u * N_);
    const float2* __restrict__ P1 = (const float2*)(g_Bh + 1u * N_);
    const float2* __restrict__ P2 = (const float2*)(g_Bh + 2u * N_);
    const float2* __restrict__ P3 = (const float2*)(g_Bh + 3u * N_);
    const float2* __restrict__ P4 = (const float2*)(g_Bh + 4u * N_);

    float4 S0 = {0,0,0,0}, S1 = {0,0,0,0}, S2 = {0,0,0,0},
           S3 = {0,0,0,0}, S4 = {0,0,0,0};

#pragma unroll
    for (int dd = d0 - R_; dd < d0 + R_; dd++) {
        if (dd >= 0 && dd < D_) {
            const int o = dd * HW4 + q;
            float4 v;
            v = ld4h(P0,o); S0.x+=v.x; S0.y+=v.y; S0.z+=v.z; S0.w+=v.w;
            v = ld4h(P1,o); S1.x+=v.x; S1.y+=v.y; S1.z+=v.z; S1.w+=v.w;
            v = ld4h(P2,o); S2.x+=v.x; S2.y+=v.y; S2.z+=v.z; S2.w+=v.w;
            v = ld4h(P3,o); S3.x+=v.x; S3.y+=v.y; S3.z+=v.z; S3.w+=v.w;
            v = ld4h(P4,o); S4.x+=v.x; S4.y+=v.y; S4.z+=v.z; S4.w+=v.w;
        }
    }

    float acc = 0.f;
    for (int d = d0; d < d0 + DCHUNK; d++) {
        const int dn = d + R_;
        if (dn < D_) {
            const int o = dn * HW4 + q;
            float4 v;
            v = ld4h(P0,o); S0.x+=v.x; S0.y+=v.y; S0.z+=v.z; S0.w+=v.w;
            v = ld4h(P1,o); S1.x+=v.x; S1.y+=v.y; S1.z+=v.z; S1.w+=v.w;
            v = ld4h(P2,o); S2.x+=v.x; S2.y+=v.y; S2.z+=v.z; S2.w+=v.w;
            v = ld4h(P3,o); S3.x+=v.x; S3.y+=v.y; S3.z+=v.z; S3.w+=v.w;
            v = ld4h(P4,o); S4.x+=v.x; S4.y+=v.y; S4.z+=v.z; S4.w+=v.w;
        }
        acc += ccf(S0.x, S1.x, S2.x, S3.x, S4.x);
        acc += ccf(S0.y, S1.y, S2.y, S3.y, S4.y);
        acc += ccf(S0.z, S1.z, S2.z, S3.z, S4.z);
        acc += ccf(S0.w, S1.w, S2.w, S3.w, S4.w);

        const int dp = d - R_;
        if (dp >= 0) {
            const int o = dp * HW4 + q;
            float4 v;
            v = ld4h(P0,o); S0.x-=v.x; S0.y-=v.y; S0.z-=v.z; S0.w-=v.w;
            v = ld4h(P1,o); S1.x-=v.x; S1.y-=v.y; S1.z-=v.z; S1.w-=v.w;
            v = ld4h(P2,o); S2.x-=v.x; S2.y-=v.y; S2.z-=v.z; S2.w-=v.w;
            v = ld4h(P3,o); S3.x-=v.x; S3.y-=v.y; S3.z-=v.z; S3.w-=v.w;
            v = ld4h(P4,o); S4.x-=v.x; S4.y-=v.y; S4.z-=v.z; S4.w-=v.w;
        }
    }

    __shared__ float sh[512];
    sh[t] = acc;
    __syncthreads();
#pragma unroll
    for (int s = 256; s > 0; s >>= 1) {
        if (t < s) sh[t] += sh[t + s];
        __syncthreads();
    }
    if (t == 0) g_ccpart[blockIdx.y * GRID3X + blockIdx.x] = sh[0];

    // ----- last-block final combine -----
    __shared__ bool is_last;
    if (t == 0) {
        __threadfence();
        is_last = (atomicAdd(&g_cnt, 1u) == NPART3 - 1);
    }
    __syncthreads();
    if (!is_last) return;

    float cc = 0.f;
    for (int i = t; i < NPART3; i += 512) cc += g_ccpart[i];

    const float invNH = 1.0f / (3.0f * D_ * (H_ - 1) * W_);
    const float invND = 1.0f / (3.0f * (D_ - 1) * H_ * W_);
    const float invNW = 1.0f / (3.0f * D_ * H_ * (W_ - 1));

    float g = 0.f;
    for (int i = t; i < GBLK; i += 512) {
        g += g_gpart[i * 3 + 0] * invNH
           + g_gpart[i * 3 + 1] * invND
           + g_gpart[i * 3 + 2] * invNW;
    }

    __shared__ float shg[512];
    sh[t] = cc;
    shg[t] = g;
    __syncthreads();
#pragma unroll
    for (int s = 256; s > 0; s >>= 1) {
        if (t < s) { sh[t] += sh[t + s]; shg[t] += shg[t + s]; }
        __syncthreads();
    }
    if (t == 0)
        out[0] = (1.0f - sh[0] / (float)N_) + 0.01f * (shg[0] / 3.0f);
}

extern "C" void kernel_launch(void* const* d_in, const int* in_sizes, int n_in,
                              void* d_out, int out_size)
{
    const float* I   = (const float*)d_in[0];
    const float* J   = (const float*)d_in[1];
    const float* dsp = (const float*)d_in[2];
    float* out = (float*)d_out;

    k_A<<<NBLK_WH + GBLK, TPB1>>>(I, J, dsp);
    k_B<<<dim3(GRID3X, GRID3Y), 512>>>(out);
}

// round 8
// speedup vs baseline: 2.5086x; 1.0730x over previous
#include <cuda_runtime.h>
#include <cuda_fp16.h>

#define D_ 160
#define H_ 192
#define W_ 160
#define HW_ (H_ * W_)
#define N_ (D_ * H_ * W_)          // 4,915,200
#define R_ 4
#define WSZ 729.0f

#define W2 (W_ / 2)                 // 80 float2 lanes per row
#define HSUB 24                     // output rows per 80-lane group
#define NHCH (H_ / (2 * HSUB))      // 4 (each block = 2 groups = 48 rows)
#define NBLK_WH (D_ * NHCH)         // 640
#define GBLK 768
#define TPB1 160

#define DCHUNK 8
#define HW2 (HW_ / 2)               // 15360 half2 positions per slice
#define GRID3X (HW2 / 512)          // 30
#define GRID3Y (D_ / DCHUNK)        // 20
#define NPART3 (GRID3X * GRID3Y)    // 600

// Scratch — W+H box sums in fp16 (values <= 81; cancellation-heavy math stays fp32)
__device__ __half g_Bh[5u * N_];
__device__ float g_ccpart[NPART3];
__device__ float g_gpart[GBLK * 3];
__device__ unsigned int g_cnt;

__device__ __forceinline__ float ccf(float s0, float s1, float s2, float s3, float s4)
{
    const float uI = s0 * (1.0f / WSZ);
    const float uJ = s1 * (1.0f / WSZ);
    const float cross = s4 - uJ * s0 - uI * s1 + uI * uJ * WSZ;
    const float Iv = s2 - 2.0f * uI * s0 + uI * uI * WSZ;
    const float Jv = s3 - 2.0f * uJ * s1 + uJ * uJ * WSZ;
    return cross * cross / (Iv * Jv + 1e-5f);
}

// ---------------------------------------------------------------------------
// Kernel 1, blocks [0, NBLK_WH): fused W+H box-sum, 2 voxels/thread.
// 160 threads = 2 groups x 80 lanes; each group owns an HSUB-row subchunk.
// Ping-pong float2 row buffers (1 sync/row), fp16 half2 ring for H window.
// Running H sums accumulate the unrounded fp32 W-sums; the ring stores the
// rounded value only for the trailing-edge subtract (drift << fp16 out ulp).
// Blocks [NBLK_WH, +GBLK): gradient-loss partials.
// ---------------------------------------------------------------------------
__global__ void __launch_bounds__(TPB1) k_A(const float* __restrict__ I,
                                            const float* __restrict__ J,
                                            const float* __restrict__ dsp)
{
    const int bid = blockIdx.x;
    const int tid = threadIdx.x;

    if (bid == 0 && tid == 0) g_cnt = 0u;   // reset for graph replay

    if (bid < NBLK_WH) {
        __shared__ float2  bI[2][2][W2 + 4];   // [group][pp][cell]
        __shared__ float2  bJ[2][2][W2 + 4];
        __shared__ __half2 ring[2][9][5][W2];

        const int g    = tid / W2;             // 0 or 1
        const int lane = tid % W2;             // 0..79
        const int d    = bid / NHCH;
        const int hg0  = (bid % NHCH) * (2 * HSUB) + g * HSUB;

        if (lane < 2) {
#pragma unroll
            for (int pp = 0; pp < 2; pp++) {
                bI[g][pp][lane] = make_float2(0.f, 0.f);
                bI[g][pp][W2 + 2 + lane] = make_float2(0.f, 0.f);
                bJ[g][pp][lane] = make_float2(0.f, 0.f);
                bJ[g][pp][W2 + 2 + lane] = make_float2(0.f, 0.f);
            }
        }

        const float2* __restrict__ I2p = (const float2*)(I + (size_t)d * HW_);
        const float2* __restrict__ J2p = (const float2*)(J + (size_t)d * HW_);

        float2 S0 = {0.f,0.f}, S1 = {0.f,0.f}, S2 = {0.f,0.f},
               S3 = {0.f,0.f}, S4 = {0.f,0.f};

        {   // preload first row (hg0-R) into pp buffer 0
            const int h = hg0 - R_;
            float2 a = {0.f,0.f}, b = {0.f,0.f};
            if (h >= 0) { a = I2p[h * W2 + lane]; b = J2p[h * W2 + lane]; }
            bI[g][0][lane + 2] = a;
            bJ[g][0][lane + 2] = b;
        }
        __syncthreads();

        int cur = 0;
        for (int h = hg0 - R_; h < hg0 + HSUB + R_; h++) {
            // prefetch next row
            float2 nI = {0.f,0.f}, nJ = {0.f,0.f};
            const int hn = h + 1;
            if (hn >= 0 && hn < H_) {
                nI = I2p[hn * W2 + lane];
                nJ = J2p[hn * W2 + lane];
            }

            // gather 10 input values per array (5 aligned float2 cells)
            float vI[10], vJ[10];
#pragma unroll
            for (int j = 0; j < 5; j++) {
                const float2 cI = bI[g][cur][lane + j];
                const float2 cJ = bJ[g][cur][lane + j];
                vI[2*j] = cI.x; vI[2*j+1] = cI.y;
                vJ[2*j] = cJ.x; vJ[2*j+1] = cJ.y;
            }

            // even output = taps 0..8; odd = even - ch(0) + ch(9)
            float e0=0.f,e1=0.f,e2=0.f,e3=0.f,e4=0.f;
#pragma unroll
            for (int i = 0; i < 9; i++) {
                const float a = vI[i], b = vJ[i];
                e0 += a; e1 += b; e2 += a*a; e3 += b*b; e4 += a*b;
            }
            const float o0 = e0 - vI[0] + vI[9];
            const float o1 = e1 - vJ[0] + vJ[9];
            const float o2 = e2 - vI[0]*vI[0] + vI[9]*vI[9];
            const float o3 = e3 - vJ[0]*vJ[0] + vJ[9]*vJ[9];
            const float o4 = e4 - vI[0]*vJ[0] + vI[9]*vJ[9];

            // accumulate unrounded; store rounded for trailing subtract
            const int slot = (h + 27) % 9;
            ring[g][slot][0][lane] = __floats2half2_rn(e0, o0); S0.x += e0; S0.y += o0;
            ring[g][slot][1][lane] = __floats2half2_rn(e1, o1); S1.x += e1; S1.y += o1;
            ring[g][slot][2][lane] = __floats2half2_rn(e2, o2); S2.x += e2; S2.y += o2;
            ring[g][slot][3][lane] = __floats2half2_rn(e3, o3); S3.x += e3; S3.y += o3;
            ring[g][slot][4][lane] = __floats2half2_rn(e4, o4); S4.x += e4; S4.y += o4;

            const int ho = h - R_;
            if (ho >= hg0 && ho < hg0 + HSUB) {
                const size_t ob = ((size_t)d * HW_ + (size_t)ho * W_) >> 1;
                __half2* __restrict__ o = (__half2*)g_Bh;
                o[(0u*N_>>1) + ob + lane] = __floats2half2_rn(S0.x, S0.y);
                o[(1u*N_>>1) + ob + lane] = __floats2half2_rn(S1.x, S1.y);
                o[(2u*N_>>1) + ob + lane] = __floats2half2_rn(S2.x, S2.y);
                o[(3u*N_>>1) + ob + lane] = __floats2half2_rn(S3.x, S3.y);
                o[(4u*N_>>1) + ob + lane] = __floats2half2_rn(S4.x, S4.y);
            }
            const int hl = h - 2 * R_;
            if (hl >= hg0 - R_) {
                const int ls = (hl + 27) % 9;
                float2 f;
                f = __half22float2(ring[g][ls][0][lane]); S0.x -= f.x; S0.y -= f.y;
                f = __half22float2(ring[g][ls][1][lane]); S1.x -= f.x; S1.y -= f.y;
                f = __half22float2(ring[g][ls][2][lane]); S2.x -= f.x; S2.y -= f.y;
                f = __half22float2(ring[g][ls][3][lane]); S3.x -= f.x; S3.y -= f.y;
                f = __half22float2(ring[g][ls][4][lane]); S4.x -= f.x; S4.y -= f.y;
            }

            bI[g][cur ^ 1][lane + 2] = nI;
            bJ[g][cur ^ 1][lane + 2] = nJ;
            __syncthreads();
            cur ^= 1;
        }
    } else {
        // ----- gradient-loss partials (float4 vectorized) -----
        const int gid = bid - NBLK_WH;
        const int W4 = W_ / 4;
        const int NV = N_ / 4;
        const int total = 3 * NV;
        const float4* __restrict__ p4 = (const float4*)dsp;
        const float*  __restrict__ pf = dsp;
        const int w = tid;

        float aH = 0.f, aD = 0.f, aW = 0.f;
        for (int i = gid * TPB1 + w; i < total; i += GBLK * TPB1) {
            const int r  = i % NV;
            const int wv = r % W4;
            const int h  = (r / W4) % H_;
            const int d  = r / (W4 * H_);

            const float4 v = p4[i];
            float t;
            t = v.y - v.x; aW += t * t;
            t = v.z - v.y; aW += t * t;
            t = v.w - v.z; aW += t * t;
            if (wv < W4 - 1) { t = pf[i * 4 + 4] - v.w; aW += t * t; }
            if (h < H_ - 1) {
                const float4 u = p4[i + W4];
                t = u.x - v.x; aH += t * t;
                t = u.y - v.y; aH += t * t;
                t = u.z - v.z; aH += t * t;
                t = u.w - v.w; aH += t * t;
            }
            if (d < D_ - 1) {
                const float4 u = p4[i + HW_ / 4];
                t = u.x - v.x; aD += t * t;
                t = u.y - v.y; aD += t * t;
                t = u.z - v.z; aD += t * t;
                t = u.w - v.w; aD += t * t;
            }
        }

        __shared__ float sh[3][TPB1];
        sh[0][w] = aH; sh[1][w] = aD; sh[2][w] = aW;
        __syncthreads();
        if (w < 80) { sh[0][w] += sh[0][w+80]; sh[1][w] += sh[1][w+80]; sh[2][w] += sh[2][w+80]; }
        __syncthreads();
        if (w < 40) { sh[0][w] += sh[0][w+40]; sh[1][w] += sh[1][w+40]; sh[2][w] += sh[2][w+40]; }
        __syncthreads();
        if (w < 20) { sh[0][w] += sh[0][w+20]; sh[1][w] += sh[1][w+20]; sh[2][w] += sh[2][w+20]; }
        __syncthreads();
        if (w < 10) { sh[0][w] += sh[0][w+10]; sh[1][w] += sh[1][w+10]; sh[2][w] += sh[2][w+10]; }
        __syncthreads();
        if (w < 5)  { sh[0][w] += sh[0][w+5];  sh[1][w] += sh[1][w+5];  sh[2][w] += sh[2][w+5];  }
        __syncthreads();
        if (w == 0) {
            g_gpart[gid * 3 + 0] = sh[0][0] + sh[0][1] + sh[0][2] + sh[0][3] + sh[0][4];
            g_gpart[gid * 3 + 1] = sh[1][0] + sh[1][1] + sh[1][2] + sh[1][3] + sh[1][4];
            g_gpart[gid * 3 + 2] = sh[2][0] + sh[2][1] + sh[2][2] + sh[2][3] + sh[2][4];
        }
    }
}

// ---------------------------------------------------------------------------
// Kernel 2: D-axis running box sum over half2 (2 voxels/thread) fused with
// the cc formula + block reduction; last finishing block does final combine.
// grid = (30, 20), block = 512.  (R6-proven geometry.)
// ---------------------------------------------------------------------------
__global__ void __launch_bounds__(512) k_B(float* __restrict__ out)
{
    const int t = threadIdx.x;
    const int p  = blockIdx.x * 512 + t;     // half2 position in a slice
    const int d0 = blockIdx.y * DCHUNK;

    const __half2* __restrict__ P0 = (const __half2*)(g_Bh + 0u * N_);
    const __half2* __restrict__ P1 = (const __half2*)(g_Bh + 1u * N_);
    const __half2* __restrict__ P2 = (const __half2*)(g_Bh + 2u * N_);
    const __half2* __restrict__ P3 = (const __half2*)(g_Bh + 3u * N_);
    const __half2* __restrict__ P4 = (const __half2*)(g_Bh + 4u * N_);

    float2 S0 = {0.f, 0.f}, S1 = {0.f, 0.f}, S2 = {0.f, 0.f},
           S3 = {0.f, 0.f}, S4 = {0.f, 0.f};

#pragma unroll
    for (int dd = d0 - R_; dd < d0 + R_; dd++) {
        if (dd >= 0 && dd < D_) {
            const int o = dd * HW2 + p;
            float2 v;
            v = __half22float2(P0[o]); S0.x += v.x; S0.y += v.y;
            v = __half22float2(P1[o]); S1.x += v.x; S1.y += v.y;
            v = __half22float2(P2[o]); S2.x += v.x; S2.y += v.y;
            v = __half22float2(P3[o]); S3.x += v.x; S3.y += v.y;
            v = __half22float2(P4[o]); S4.x += v.x; S4.y += v.y;
        }
    }

    float acc = 0.f;
    for (int d = d0; d < d0 + DCHUNK; d++) {
        const int dn = d + R_;
        if (dn < D_) {
            const int o = dn * HW2 + p;
            float2 v;
            v = __half22float2(P0[o]); S0.x += v.x; S0.y += v.y;
            v = __half22float2(P1[o]); S1.x += v.x; S1.y += v.y;
            v = __half22float2(P2[o]); S2.x += v.x; S2.y += v.y;
            v = __half22float2(P3[o]); S3.x += v.x; S3.y += v.y;
            v = __half22float2(P4[o]); S4.x += v.x; S4.y += v.y;
        }
        acc += ccf(S0.x, S1.x, S2.x, S3.x, S4.x);
        acc += ccf(S0.y, S1.y, S2.y, S3.y, S4.y);

        const int dp = d - R_;
        if (dp >= 0) {
            const int o = dp * HW2 + p;
            float2 v;
            v = __half22float2(P0[o]); S0.x -= v.x; S0.y -= v.y;
            v = __half22float2(P1[o]); S1.x -= v.x; S1.y -= v.y;
            v = __half22float2(P2[o]); S2.x -= v.x; S2.y -= v.y;
            v = __half22float2(P3[o]); S3.x -= v.x; S3.y -= v.y;
            v = __half22float2(P4[o]); S4.x -= v.x; S4.y -= v.y;
        }
    }

    __shared__ float sh[512];
    sh[t] = acc;
    __syncthreads();
#pragma unroll
    for (int s = 256; s > 0; s >>= 1) {
        if (t < s) sh[t] += sh[t + s];
        __syncthreads();
    }
    if (t == 0) g_ccpart[blockIdx.y * GRID3X + blockIdx.x] = sh[0];

    // ----- last-block final combine -----
    __shared__ bool is_last;
    if (t == 0) {
        __threadfence();
        is_last = (atomicAdd(&g_cnt, 1u) == NPART3 - 1);
    }
    __syncthreads();
    if (!is_last) return;

    float cc = 0.f;
    for (int i = t; i < NPART3; i += 512) cc += g_ccpart[i];

    const float invNH = 1.0f / (3.0f * D_ * (H_ - 1) * W_);
    const float invND = 1.0f / (3.0f * (D_ - 1) * H_ * W_);
    const float invNW = 1.0f / (3.0f * D_ * H_ * (W_ - 1));

    float g = 0.f;
    for (int i = t; i < GBLK; i += 512) {
        g += g_gpart[i * 3 + 0] * invNH
           + g_gpart[i * 3 + 1] * invND
           + g_gpart[i * 3 + 2] * invNW;
    }

    __shared__ float shg[512];
    sh[t] = cc;
    shg[t] = g;
    __syncthreads();
#pragma unroll
    for (int s = 256; s > 0; s >>= 1) {
        if (t < s) { sh[t] += sh[t + s]; shg[t] += shg[t + s]; }
        __syncthreads();
    }
    if (t == 0)
        out[0] = (1.0f - sh[0] / (float)N_) + 0.01f * (shg[0] / 3.0f);
}

extern "C" void kernel_launch(void* const* d_in, const int* in_sizes, int n_in,
                              void* d_out, int out_size)
{
    const float* I   = (const float*)d_in[0];
    const float* J   = (const float*)d_in[1];
    const float* dsp = (const float*)d_in[2];
    float* out = (float*)d_out;

    k_A<<<NBLK_WH + GBLK, TPB1>>>(I, J, dsp);
    k_B<<<dim3(GRID3X, GRID3Y), 512>>>(out);
}